// round 16
// baseline (speedup 1.0000x reference)
#include <cuda_runtime.h>
#include <cuda_fp16.h>
#include <cstdint>

#define NN   10000
#define EE   320000
#define FDIM 256
#define CDIM 40

// ---------------- scratch (device globals; no allocation allowed) ----------------
__device__ int   g_is64;
__device__ int   g_deg[NN];
__device__ int   g_rowptr[NN + 1];
__device__ int   g_cursor[NN];
__device__ float g_dinv[NN];
__device__ int   g_col[EE];
__device__ float g_wn[EE];
__device__ __align__(16) __half g_xh[NN * FDIM];        // fp16 copy of input x
__device__ __align__(16) __half g_w16[4 * FDIM * FDIM]; // fp16 copies of W1..W4
__device__ __align__(16) __half g_hAh[NN * FDIM];       // node features (fp16)
__device__ __align__(16) __half g_hBh[NN * FDIM];
__device__ __align__(16) __half g_hwh[NN * FDIM];       // GEMM output (messages), fp16

__device__ __forceinline__ __half* hbuf(int id) {
    switch (id) {
        case 0: return g_hAh;
        case 1: return g_hBh;
        case 2: return g_xh;
    }
    return nullptr;
}

__device__ __forceinline__ int eidx(const void* ei, int i) {
    if (g_is64) return (int)((const long long*)ei)[i];
    return ((const int*)ei)[i];
}

__device__ __forceinline__ uint32_t smem_u32(const void* p) {
    uint32_t a;
    asm("{ .reg .u64 t; cvta.to.shared.u64 t, %1; cvt.u32.u64 %0, t; }"
        : "=r"(a) : "l"(p));
    return a;
}

// ---- cp.async (Ampere+ family-wide) ----
__device__ __forceinline__ void cp_async16(uint32_t dst, const void* src) {
    asm volatile("cp.async.cg.shared.global [%0], [%1], 16;"
                 :: "r"(dst), "l"(src));
}
__device__ __forceinline__ void cp_commit() {
    asm volatile("cp.async.commit_group;");
}
template <int N>
__device__ __forceinline__ void cp_wait() {
    asm volatile("cp.async.wait_group %0;" :: "n"(N));
}

// ---- warp-level MMA helpers (family-wide sm_80+ PTX) ----
__device__ __forceinline__ void ldsm_x4(uint32_t& r0, uint32_t& r1,
                                        uint32_t& r2, uint32_t& r3, uint32_t addr) {
    asm volatile("ldmatrix.sync.aligned.m8n8.x4.shared.b16 {%0,%1,%2,%3}, [%4];"
                 : "=r"(r0), "=r"(r1), "=r"(r2), "=r"(r3) : "r"(addr));
}
__device__ __forceinline__ void ldsm_x4t(uint32_t& r0, uint32_t& r1,
                                         uint32_t& r2, uint32_t& r3, uint32_t addr) {
    asm volatile("ldmatrix.sync.aligned.m8n8.x4.trans.shared.b16 {%0,%1,%2,%3}, [%4];"
                 : "=r"(r0), "=r"(r1), "=r"(r2), "=r"(r3) : "r"(addr));
}
__device__ __forceinline__ void mma16816(float* c,
                                         uint32_t a0, uint32_t a1, uint32_t a2, uint32_t a3,
                                         uint32_t b0, uint32_t b1) {
    asm volatile(
        "mma.sync.aligned.m16n8k16.row.col.f32.f16.f16.f32 "
        "{%0,%1,%2,%3}, {%4,%5,%6,%7}, {%8,%9}, {%0,%1,%2,%3};"
        : "+f"(c[0]), "+f"(c[1]), "+f"(c[2]), "+f"(c[3])
        : "r"(a0), "r"(a1), "r"(a2), "r"(a3), "r"(b0), "r"(b1));
}

// ---------------- dtype detection + graph preprocessing ----------------
__global__ void init_kernel() {
    int i = blockIdx.x * blockDim.x + threadIdx.x;
    if (i < NN) g_deg[i] = 1;   // self-loop
    if (i == 0) g_is64 = 1;
}

__global__ void detect_kernel(const unsigned* __restrict__ w) {
    int i = blockIdx.x * blockDim.x + threadIdx.x;
    if (i < EE) {
        if (w[2 * i + 1] != 0u) g_is64 = 0;
    }
}

// one-shot fp32 -> fp16 conversion of x and W1..W4
__global__ void conv_kernel(const float* __restrict__ x,
                            const float* __restrict__ W1, const float* __restrict__ W2,
                            const float* __restrict__ W3, const float* __restrict__ W4)
{
    const int NX = NN * FDIM;
    const int NW = FDIM * FDIM;
    int stride = gridDim.x * blockDim.x;
    for (int i = blockIdx.x * blockDim.x + threadIdx.x; i < NX + 4 * NW; i += stride) {
        if (i < NX) {
            g_xh[i] = __float2half_rn(x[i]);
        } else {
            int j = i - NX;
            int w = j >> 16, k = j & (NW - 1);
            const float* W = (w == 0) ? W1 : (w == 1) ? W2 : (w == 2) ? W3 : W4;
            g_w16[j] = __float2half_rn(W[k]);
        }
    }
}

__global__ void count_deg_kernel(const void* __restrict__ ei) {
    int e = blockIdx.x * blockDim.x + threadIdx.x;
    if (e < EE) {
        int d = eidx(ei, EE + e);
        if (d >= 0 && d < NN) atomicAdd(&g_deg[d], 1);
    }
}

// single-block exclusive scan of (deg-1) -> rowptr/cursor; also dinv = rsqrt(deg)
__global__ void scan_kernel() {
    const int ITEMS = 10;
    __shared__ int sdeg[10240];
    __shared__ int wsum[32];
    int t = threadIdx.x;
    for (int i = t; i < 10240; i += 1024)
        sdeg[i] = (i < NN) ? (g_deg[i] - 1) : 0;
    __syncthreads();

    int base = t * ITEMS;
    int local[ITEMS];
    int sum = 0;
#pragma unroll
    for (int i = 0; i < ITEMS; i++) {
        int v = sdeg[base + i];
        local[i] = sum;
        sum += v;
    }
    int lane = t & 31, wid = t >> 5;
    int x = sum;
#pragma unroll
    for (int off = 1; off < 32; off <<= 1) {
        int y = __shfl_up_sync(0xffffffffu, x, off);
        if (lane >= off) x += y;
    }
    if (lane == 31) wsum[wid] = x;
    __syncthreads();
    if (wid == 0) {
        int w = wsum[lane];
#pragma unroll
        for (int off = 1; off < 32; off <<= 1) {
            int y = __shfl_up_sync(0xffffffffu, w, off);
            if (lane >= off) w += y;
        }
        wsum[lane] = w;
    }
    __syncthreads();
    int off0 = (x - sum) + (wid > 0 ? wsum[wid - 1] : 0);
#pragma unroll
    for (int i = 0; i < ITEMS; i++) {
        int idx = base + i;
        if (idx < NN) {
            int rp = off0 + local[i];
            g_rowptr[idx] = rp;
            g_cursor[idx] = rp;
            g_dinv[idx]   = rsqrtf((float)(sdeg[idx] + 1));
        }
    }
    if (t == 1023) g_rowptr[NN] = off0 + sum;
}

__global__ void fill_kernel(const void* __restrict__ ei) {
    int e = blockIdx.x * blockDim.x + threadIdx.x;
    if (e < EE) {
        int s = eidx(ei, e);
        int d = eidx(ei, EE + e);
        if (s >= 0 && s < NN && d >= 0 && d < NN) {
            int pos = atomicAdd(&g_cursor[d], 1);
            g_col[pos] = s;
            g_wn[pos]  = g_dinv[s] * g_dinv[d];
        }
    }
}

// ---------------- HMMA GEMM (fp16 in, Nn==256): g_hwh = A16[M,256] @ W16[layer] ----------------
// CTA tile 64x256, BK=16, 256 threads (8 warps), 157 CTAs. 4-stage cp.async pipeline.
#define GBM 64
#define STAGES 4

__global__ __launch_bounds__(256) void gemm_kernel(int a_id, int w_layer)
{
    const int K = FDIM, Nn = FDIM;
    const __half* A = hbuf(a_id);
    const __half* W = g_w16 + (size_t)w_layer * FDIM * FDIM;
    __half* C = g_hwh;

    __shared__ __half Ast[STAGES][GBM][24];   // row stride 48 B, conflict-free
    __shared__ __half Bs[STAGES][16][264];    // row stride 528 B, conflict-free

    int tid = threadIdx.x;
    int lane = tid & 31, w = tid >> 5;
    int mt = w & 3;            // m-tile (16 rows)
    int nh = w >> 2;           // n half (128 cols)
    int m0 = blockIdx.x * GBM;

    float acc[16][4];
#pragma unroll
    for (int j = 0; j < 16; j++)
#pragma unroll
        for (int q = 0; q < 4; q++) acc[j][q] = 0.f;

    int a_row = tid >> 1, a_h8 = (tid & 1) << 3;
    int a_gr = min(m0 + a_row, NN - 1);           // clamp; bad rows discarded in epilogue
    uint32_t a_dst0 = smem_u32(&Ast[0][a_row][a_h8]);
    int b_kr[2], b_c8[2];
    uint32_t b_dst0[2];
#pragma unroll
    for (int l = 0; l < 2; l++) {
        int idx = tid * 2 + l;
        b_kr[l] = idx >> 5;
        b_c8[l] = (idx & 31) << 3;
        b_dst0[l] = smem_u32(&Bs[0][b_kr[l]][b_c8[l]]);
    }
    const uint32_t ASTG = GBM * 24 * 2;
    const uint32_t BSTG = 16 * 264 * 2;

    const int NCHUNK = K / 16;                // 16
#pragma unroll
    for (int c = 0; c < STAGES - 1; c++) {
        if (tid < 128)
            cp_async16(a_dst0 + c * ASTG, A + (size_t)a_gr * K + c * 16 + a_h8);
#pragma unroll
        for (int l = 0; l < 2; l++)
            cp_async16(b_dst0[l] + c * BSTG, W + (size_t)(c * 16 + b_kr[l]) * Nn + b_c8[l]);
        cp_commit();
    }

    for (int c = 0; c < NCHUNK; c++) {
        cp_wait<STAGES - 2>();
        __syncthreads();
        int s = c & (STAGES - 1);
        {
            uint32_t abase = smem_u32(&Ast[s][0][0]);
            int r = lane & 15, koff = (lane >> 4) << 3;
            uint32_t a_addr = abase + (uint32_t)(((mt * 16 + r) * 24 + koff) << 1);
            uint32_t a0, a1, a2, a3;
            ldsm_x4(a0, a1, a2, a3, a_addr);

            uint32_t bbase = smem_u32(&Bs[s][0][0]);
            int kr = lane & 15, nc8 = (lane >> 4) << 3;
#pragma unroll
            for (int j = 0; j < 8; j++) {
                int n0 = nh * 128 + j * 16;
                uint32_t b_addr = bbase + (uint32_t)((kr * 264 + n0 + nc8) << 1);
                uint32_t b0, b1, b2, b3;
                ldsm_x4t(b0, b1, b2, b3, b_addr);
                mma16816(acc[2 * j + 0], a0, a1, a2, a3, b0, b1);
                mma16816(acc[2 * j + 1], a0, a1, a2, a3, b2, b3);
            }
        }
        int cn = c + STAGES - 1;
        if (cn < NCHUNK) {
            int sn = cn & (STAGES - 1);
            if (tid < 128)
                cp_async16(a_dst0 + sn * ASTG, A + (size_t)a_gr * K + cn * 16 + a_h8);
#pragma unroll
            for (int l = 0; l < 2; l++)
                cp_async16(b_dst0[l] + sn * BSTG, W + (size_t)(cn * 16 + b_kr[l]) * Nn + b_c8[l]);
        }
        cp_commit();
    }

    int tr = lane >> 2, tc = (lane & 3) << 1;
    int row0 = m0 + mt * 16 + tr;
    int row1 = row0 + 8;
#pragma unroll
    for (int j = 0; j < 16; j++) {
        int n0 = nh * 128 + j * 8 + tc;
        if (row0 < NN) {
            __half2 h = __floats2half2_rn(acc[j][0], acc[j][1]);
            *(__half2*)(C + (size_t)row0 * Nn + n0) = h;
        }
        if (row1 < NN) {
            __half2 h = __floats2half2_rn(acc[j][2], acc[j][3]);
            *(__half2*)(C + (size_t)row1 * Nn + n0) = h;
        }
    }
}

// ---------------- small GEMM for layer 5 (Nn=40): g_hwh[M,40] = A16 @ W5 ----------------
#define BM 80
#define BK 16
__global__ __launch_bounds__(320) void gemm40_kernel(int a_id, const float* __restrict__ W)
{
    const int K = FDIM, Nn = CDIM;
    const __half* A = hbuf(a_id);
    __half* C = g_hwh;

    __shared__ float As[BK][BM + 4];
    __shared__ float Bsm[BK][CDIM + 2];

    int tid = threadIdx.x;
    int tx = tid & 7;
    int ty = tid >> 3;
    int m0 = blockIdx.x * BM;

    float acc[2][5];
#pragma unroll
    for (int i = 0; i < 2; i++)
#pragma unroll
        for (int j = 0; j < 5; j++) acc[i][j] = 0.f;

    for (int k0 = 0; k0 < K; k0 += BK) {
        {
            int row = tid >> 2, kc = (tid & 3) << 2;
            uint2 u = *(const uint2*)(A + (size_t)(m0 + row) * K + k0 + kc);
            const __half2* hh = (const __half2*)&u;
            float2 f0 = __half22float2(hh[0]);
            float2 f1 = __half22float2(hh[1]);
            As[kc + 0][row] = f0.x;
            As[kc + 1][row] = f0.y;
            As[kc + 2][row] = f1.x;
            As[kc + 3][row] = f1.y;
        }
#pragma unroll
        for (int l = 0; l < 2; l++) {
            int idx = tid + l * 320;
            int kr = idx / CDIM, cc = idx - kr * CDIM;
            Bsm[kr][cc] = W[(size_t)(k0 + kr) * Nn + cc];
        }
        __syncthreads();
#pragma unroll
        for (int kk = 0; kk < BK; kk++) {
            float br[5];
#pragma unroll
            for (int j = 0; j < 5; j++) br[j] = Bsm[kk][tx * 5 + j];
            float a0 = As[kk][ty * 2 + 0];
            float a1 = As[kk][ty * 2 + 1];
#pragma unroll
            for (int j = 0; j < 5; j++) {
                acc[0][j] = fmaf(a0, br[j], acc[0][j]);
                acc[1][j] = fmaf(a1, br[j], acc[1][j]);
            }
        }
        __syncthreads();
    }
#pragma unroll
    for (int i = 0; i < 2; i++) {
        int row = m0 + ty * 2 + i;
        __half* cp = C + (size_t)row * Nn + tx * 5;
#pragma unroll
        for (int j = 0; j < 5; j++) cp[j] = __float2half_rn(acc[i][j]);
    }
}

// ---------------- aggregation (256 feats): warp per node, fp16 gather + fp16 out ----------------
__global__ void agg256_kernel(const float* __restrict__ bias, int out_id, int relu)
{
    int node = (blockIdx.x * blockDim.x + threadIdx.x) >> 5;
    if (node >= NN) return;
    __half* out = hbuf(out_id);
    int lane = threadIdx.x & 31;
    int beg = g_rowptr[node], end = g_rowptr[node + 1];

    float dv = g_dinv[node];
    float wself = dv * dv;

    float acc[8];
    {
        uint4 v = ((const uint4*)(g_hwh + (size_t)node * FDIM))[lane];
        const __half2* h = (const __half2*)&v;
#pragma unroll
        for (int q = 0; q < 4; q++) {
            float2 f = __half22float2(h[q]);
            acc[2 * q + 0] = wself * f.x;
            acc[2 * q + 1] = wself * f.y;
        }
    }

#pragma unroll 4
    for (int e = beg; e < end; e++) {
        int s = g_col[e];
        float w = g_wn[e];
        uint4 v = ((const uint4*)(g_hwh + (size_t)s * FDIM))[lane];
        const __half2* h = (const __half2*)&v;
#pragma unroll
        for (int q = 0; q < 4; q++) {
            float2 f = __half22float2(h[q]);
            acc[2 * q + 0] = fmaf(w, f.x, acc[2 * q + 0]);
            acc[2 * q + 1] = fmaf(w, f.y, acc[2 * q + 1]);
        }
    }
    float4 b0 = ((const float4*)bias)[lane * 2];
    float4 b1 = ((const float4*)bias)[lane * 2 + 1];
    float o[8] = {acc[0] + b0.x, acc[1] + b0.y, acc[2] + b0.z, acc[3] + b0.w,
                  acc[4] + b1.x, acc[5] + b1.y, acc[6] + b1.z, acc[7] + b1.w};
    if (relu) {
#pragma unroll
        for (int q = 0; q < 8; q++) o[q] = fmaxf(o[q], 0.f);
    }
    __half2 h2[4];
#pragma unroll
    for (int q = 0; q < 4; q++) h2[q] = __floats2half2_rn(o[2 * q], o[2 * q + 1]);
    *(uint4*)(out + (size_t)node * FDIM + lane * 8) = *(uint4*)h2;
}

// ---------------- layer5: aggregation (40 feats) + log_softmax fused ----------------
__global__ void agg40_lsm_kernel(const float* __restrict__ bias,
                                 float* __restrict__ out, int write_logits)
{
    int node = (blockIdx.x * blockDim.x + threadIdx.x) >> 5;
    if (node >= NN) return;
    int lane = threadIdx.x & 31;
    int beg = g_rowptr[node], end = g_rowptr[node + 1];

    float dv = g_dinv[node];
    float wself = dv * dv;
    const __half* hw = g_hwh;

    const __half* hp = hw + (size_t)node * CDIM;
    float a0 = wself * __half2float(hp[lane]);
    float a1 = (lane < CDIM - 32) ? wself * __half2float(hp[lane + 32]) : 0.f;

    for (int e = beg; e < end; e++) {
        int s = g_col[e];
        float w = g_wn[e];
        const __half* p = hw + (size_t)s * CDIM;
        a0 = fmaf(w, __half2float(p[lane]), a0);
        if (lane < CDIM - 32) a1 = fmaf(w, __half2float(p[lane + 32]), a1);
    }
    float v0 = a0 + bias[lane];
    float v1 = (lane < CDIM - 32) ? a1 + bias[lane + 32] : -1e30f;

    float m = fmaxf(v0, v1);
#pragma unroll
    for (int off = 16; off > 0; off >>= 1)
        m = fmaxf(m, __shfl_xor_sync(0xffffffffu, m, off));
    float s = __expf(v0 - m) + ((lane < CDIM - 32) ? __expf(v1 - m) : 0.f);
#pragma unroll
    for (int off = 16; off > 0; off >>= 1)
        s += __shfl_xor_sync(0xffffffffu, s, off);
    float lse = m + __logf(s);

    float* op = out + (size_t)node * CDIM;
    op[lane] = v0 - lse;
    if (lane < CDIM - 32) op[lane + 32] = v1 - lse;
    if (write_logits) {
        float* lo = out + (size_t)NN * CDIM + (size_t)node * CDIM;
        lo[lane] = v0;
        if (lane < CDIM - 32) lo[lane + 32] = v1;
    }
}

// ---------------- host ----------------
extern "C" void kernel_launch(void* const* d_in, const int* in_sizes, int n_in,
                              void* d_out, int out_size)
{
    const float* x  = (const float*)d_in[0];
    const void*  ei = d_in[1];
    const float* W1 = (const float*)d_in[2];  const float* b1 = (const float*)d_in[3];
    const float* W2 = (const float*)d_in[4];  const float* b2 = (const float*)d_in[5];
    const float* W3 = (const float*)d_in[6];  const float* b3 = (const float*)d_in[7];
    const float* W4 = (const float*)d_in[8];  const float* b4 = (const float*)d_in[9];
    const float* W5 = (const float*)d_in[10]; const float* b5 = (const float*)d_in[11];
    float* out = (float*)d_out;

    const int EB = (EE + 255) / 256;
    const int AGGB = (NN * 32 + 255) / 256;    // warp per node
    const int GB = (NN + GBM - 1) / GBM;       // 157 CTAs
    const int GB40 = NN / BM;                  // 125 CTAs

    // hbuf ids: 0=g_hAh, 1=g_hBh, 2=g_xh
    init_kernel<<<(NN + 255) / 256, 256>>>();                 // 1
    detect_kernel<<<EB, 256>>>((const unsigned*)ei);          // 2
    conv_kernel<<<592, 256>>>(x, W1, W2, W3, W4);             // 3
    gemm_kernel<<<GB, 256>>>(2, 0);                           // 4  <- profiled
    count_deg_kernel<<<EB, 256>>>(ei);                        // 5
    scan_kernel<<<1, 1024>>>();                               // 6
    fill_kernel<<<EB, 256>>>(ei);                             // 7
    agg256_kernel<<<AGGB, 256>>>(b1, 0, 1);                   // 8

    gemm_kernel<<<GB, 256>>>(0, 1);
    agg256_kernel<<<AGGB, 256>>>(b2, 1, 1);
    gemm_kernel<<<GB, 256>>>(1, 2);
    agg256_kernel<<<AGGB, 256>>>(b3, 0, 1);
    gemm_kernel<<<GB, 256>>>(0, 3);
    agg256_kernel<<<AGGB, 256>>>(b4, 1, 1);
    gemm40_kernel<<<GB40, 320>>>(1, W5);
    int write_logits = (out_size >= 2 * NN * CDIM) ? 1 : 0;
    agg40_lsm_kernel<<<AGGB, 256>>>(b5, out, write_logits);

    (void)in_sizes; (void)n_in;
}

// round 17
// speedup vs baseline: 1.1306x; 1.1306x over previous
#include <cuda_runtime.h>
#include <cuda_fp16.h>
#include <cstdint>

#define NN   10000
#define EE   320000
#define FDIM 256
#define CDIM 40

// ---------------- scratch (device globals; no allocation allowed) ----------------
__device__ int   g_is64;
__device__ int   g_deg[NN];
__device__ int   g_rowptr[NN + 1];
__device__ int   g_cursor[NN];
__device__ float g_dinv[NN];
__device__ int   g_col[EE];
__device__ float g_wn[EE];
__device__ int   g_bsum[40];
__device__ int   g_boff[40];
__device__ __align__(16) __half g_xh[NN * FDIM];        // fp16 copy of input x
__device__ __align__(16) __half g_w16[4 * FDIM * FDIM]; // fp16 copies of W1..W4
__device__ __align__(16) __half g_hAh[NN * FDIM];       // node features (fp16)
__device__ __align__(16) __half g_hBh[NN * FDIM];
__device__ __align__(16) __half g_hwh[NN * FDIM];       // GEMM output (messages), fp16

__device__ __forceinline__ __half* hbuf(int id) {
    switch (id) {
        case 0: return g_hAh;
        case 1: return g_hBh;
        case 2: return g_xh;
    }
    return nullptr;
}

__device__ __forceinline__ int eidx(const void* ei, int i) {
    if (g_is64) return (int)((const long long*)ei)[i];
    return ((const int*)ei)[i];
}

__device__ __forceinline__ uint32_t smem_u32(const void* p) {
    uint32_t a;
    asm("{ .reg .u64 t; cvta.to.shared.u64 t, %1; cvt.u32.u64 %0, t; }"
        : "=r"(a) : "l"(p));
    return a;
}

// ---- cp.async (Ampere+ family-wide) ----
__device__ __forceinline__ void cp_async16(uint32_t dst, const void* src) {
    asm volatile("cp.async.cg.shared.global [%0], [%1], 16;"
                 :: "r"(dst), "l"(src));
}
__device__ __forceinline__ void cp_commit() {
    asm volatile("cp.async.commit_group;");
}
template <int N>
__device__ __forceinline__ void cp_wait() {
    asm volatile("cp.async.wait_group %0;" :: "n"(N));
}

// ---- warp-level MMA helpers (family-wide sm_80+ PTX) ----
__device__ __forceinline__ void ldsm_x4(uint32_t& r0, uint32_t& r1,
                                        uint32_t& r2, uint32_t& r3, uint32_t addr) {
    asm volatile("ldmatrix.sync.aligned.m8n8.x4.shared.b16 {%0,%1,%2,%3}, [%4];"
                 : "=r"(r0), "=r"(r1), "=r"(r2), "=r"(r3) : "r"(addr));
}
__device__ __forceinline__ void ldsm_x4t(uint32_t& r0, uint32_t& r1,
                                         uint32_t& r2, uint32_t& r3, uint32_t addr) {
    asm volatile("ldmatrix.sync.aligned.m8n8.x4.trans.shared.b16 {%0,%1,%2,%3}, [%4];"
                 : "=r"(r0), "=r"(r1), "=r"(r2), "=r"(r3) : "r"(addr));
}
__device__ __forceinline__ void mma16816(float* c,
                                         uint32_t a0, uint32_t a1, uint32_t a2, uint32_t a3,
                                         uint32_t b0, uint32_t b1) {
    asm volatile(
        "mma.sync.aligned.m16n8k16.row.col.f32.f16.f16.f32 "
        "{%0,%1,%2,%3}, {%4,%5,%6,%7}, {%8,%9}, {%0,%1,%2,%3};"
        : "+f"(c[0]), "+f"(c[1]), "+f"(c[2]), "+f"(c[3])
        : "r"(a0), "r"(a1), "r"(a2), "r"(a3), "r"(b0), "r"(b1));
}

// ---------------- dtype detection + graph preprocessing ----------------
__global__ void init_kernel() {
    int i = blockIdx.x * blockDim.x + threadIdx.x;
    if (i < NN) g_deg[i] = 1;   // self-loop
    if (i == 0) g_is64 = 1;
}

// sample 16384 odd 32-bit words; int64 non-negative ids -> all zero.
__global__ void detect_kernel(const unsigned* __restrict__ w) {
    int i = blockIdx.x * blockDim.x + threadIdx.x;
    if (w[2 * i + 1] != 0u) g_is64 = 0;
}

// one-shot fp32 -> fp16 conversion of x and W1..W4
__global__ void conv_kernel(const float* __restrict__ x,
                            const float* __restrict__ W1, const float* __restrict__ W2,
                            const float* __restrict__ W3, const float* __restrict__ W4)
{
    const int NX = NN * FDIM;
    const int NW = FDIM * FDIM;
    int stride = gridDim.x * blockDim.x;
    for (int i = blockIdx.x * blockDim.x + threadIdx.x; i < NX + 4 * NW; i += stride) {
        if (i < NX) {
            g_xh[i] = __float2half_rn(x[i]);
        } else {
            int j = i - NX;
            int w = j >> 16, k = j & (NW - 1);
            const float* W = (w == 0) ? W1 : (w == 1) ? W2 : (w == 2) ? W3 : W4;
            g_w16[j] = __float2half_rn(W[k]);
        }
    }
}

__global__ void count_deg_kernel(const void* __restrict__ ei) {
    int e = blockIdx.x * blockDim.x + threadIdx.x;
    if (e < EE) {
        int d = eidx(ei, EE + e);
        if (d >= 0 && d < NN) atomicAdd(&g_deg[d], 1);
    }
}

// grid scan, stage 1: per-block sums of (deg-1)   [40 blocks x 256]
__global__ void scan1_kernel() {
    __shared__ int ws[8];
    int t = threadIdx.x, b = blockIdx.x;
    int i = b * 256 + t;
    int v = (i < NN) ? (g_deg[i] - 1) : 0;
    int lane = t & 31, wid = t >> 5;
    int x = v;
#pragma unroll
    for (int off = 16; off > 0; off >>= 1)
        x += __shfl_down_sync(0xffffffffu, x, off);
    if (lane == 0) ws[wid] = x;
    __syncthreads();
    if (t == 0) {
        int s = 0;
#pragma unroll
        for (int q = 0; q < 8; q++) s += ws[q];
        g_bsum[b] = s;
    }
}

// grid scan, stage 2: exclusive scan of 40 block sums  [1 block]
__global__ void scan2_kernel() {
    if (threadIdx.x == 0) {
        int s = 0;
        for (int b = 0; b < 40; b++) {
            g_boff[b] = s;
            s += g_bsum[b];
        }
        g_rowptr[NN] = s;
    }
}

// grid scan, stage 3: per-block exclusive scan + apply; also dinv  [40 x 256]
__global__ void scan3_kernel() {
    __shared__ int ws[8];
    int t = threadIdx.x, b = blockIdx.x;
    int i = b * 256 + t;
    int dg = (i < NN) ? g_deg[i] : 1;
    int v = dg - 1;
    int lane = t & 31, wid = t >> 5;
    int x = v;
#pragma unroll
    for (int off = 1; off < 32; off <<= 1) {
        int y = __shfl_up_sync(0xffffffffu, x, off);
        if (lane >= off) x += y;
    }
    if (lane == 31) ws[wid] = x;
    __syncthreads();
    if (wid == 0 && lane < 8) {
        int w = ws[lane];
#pragma unroll
        for (int off = 1; off < 8; off <<= 1) {
            int y = __shfl_up_sync(0xffu, w, off);
            if (lane >= off) w += y;
        }
        ws[lane] = w;
    }
    __syncthreads();
    int prefix = (x - v) + (wid > 0 ? ws[wid - 1] : 0);
    if (i < NN) {
        int rp = g_boff[b] + prefix;
        g_rowptr[i] = rp;
        g_cursor[i] = rp;
        g_dinv[i]   = rsqrtf((float)dg);
    }
}

__global__ void fill_kernel(const void* __restrict__ ei) {
    int e = blockIdx.x * blockDim.x + threadIdx.x;
    if (e < EE) {
        int s = eidx(ei, e);
        int d = eidx(ei, EE + e);
        if (s >= 0 && s < NN && d >= 0 && d < NN) {
            int pos = atomicAdd(&g_cursor[d], 1);
            g_col[pos] = s;
            g_wn[pos]  = g_dinv[s] * g_dinv[d];
        }
    }
}

// ---------------- HMMA GEMM (fp16 in, Nn==256): g_hwh = A16[M,256] @ W16[layer] ----------------
// CTA tile 80x256, BK=16, 320 threads (10 warps = 5 m-tiles x 2 n-halves).
// grid = 125 CTAs = single wave on 148 SMs. 4-stage cp.async pipeline. Smem 48 KB.
#define GBM 80
#define STAGES 4

__global__ __launch_bounds__(320) void gemm_kernel(int a_id, int w_layer)
{
    const int K = FDIM, Nn = FDIM;
    const __half* A = hbuf(a_id);
    const __half* W = g_w16 + (size_t)w_layer * FDIM * FDIM;
    __half* C = g_hwh;

    __shared__ __half Ast[STAGES][GBM][24];   // row stride 48 B, conflict-free (15 KB)
    __shared__ __half Bs[STAGES][16][264];    // row stride 528 B, conflict-free (33 KB)

    int tid = threadIdx.x;
    int lane = tid & 31, w = tid >> 5;
    int mt = w % 5;            // m-tile (16 rows)
    int nh = w / 5;            // n half (128 cols)
    int m0 = blockIdx.x * GBM;

    float acc[16][4];
#pragma unroll
    for (int j = 0; j < 16; j++)
#pragma unroll
        for (int q = 0; q < 4; q++) acc[j][q] = 0.f;

    // staging: A (tid<160): row=tid>>1, half-chunk=(tid&1)*8 ; B (tid<256): 2 chunks
    int a_row = tid >> 1, a_h8 = (tid & 1) << 3;
    int a_gr = min(m0 + a_row, NN - 1);           // clamp; bad rows discarded in epilogue
    uint32_t a_dst0 = smem_u32(&Ast[0][0][0]) + (uint32_t)((a_row * 24 + a_h8) << 1);
    int b_kr[2], b_c8[2];
    uint32_t b_dst0[2];
#pragma unroll
    for (int l = 0; l < 2; l++) {
        int idx = tid + l * 256;
        b_kr[l] = idx >> 5;
        b_c8[l] = (idx & 31) << 3;
        b_dst0[l] = smem_u32(&Bs[0][0][0]) + (uint32_t)((b_kr[l] * 264 + b_c8[l]) << 1);
    }
    const uint32_t ASTG = GBM * 24 * 2;
    const uint32_t BSTG = 16 * 264 * 2;

    const int NCHUNK = K / 16;                // 16
#pragma unroll
    for (int c = 0; c < STAGES - 1; c++) {
        if (tid < 160)
            cp_async16(a_dst0 + c * ASTG, A + (size_t)a_gr * K + c * 16 + a_h8);
        if (tid < 256) {
#pragma unroll
            for (int l = 0; l < 2; l++)
                cp_async16(b_dst0[l] + c * BSTG, W + (size_t)(c * 16 + b_kr[l]) * Nn + b_c8[l]);
        }
        cp_commit();
    }

    for (int c = 0; c < NCHUNK; c++) {
        cp_wait<STAGES - 2>();
        __syncthreads();
        int s = c & (STAGES - 1);
        {
            uint32_t abase = smem_u32(&Ast[s][0][0]);
            int r = lane & 15, koff = (lane >> 4) << 3;
            uint32_t a_addr = abase + (uint32_t)(((mt * 16 + r) * 24 + koff) << 1);
            uint32_t a0, a1, a2, a3;
            ldsm_x4(a0, a1, a2, a3, a_addr);

            uint32_t bbase = smem_u32(&Bs[s][0][0]);
            int kr = lane & 15, nc8 = (lane >> 4) << 3;
#pragma unroll
            for (int j = 0; j < 8; j++) {
                int n0 = nh * 128 + j * 16;
                uint32_t b_addr = bbase + (uint32_t)((kr * 264 + n0 + nc8) << 1);
                uint32_t b0, b1, b2, b3;
                ldsm_x4t(b0, b1, b2, b3, b_addr);
                mma16816(acc[2 * j + 0], a0, a1, a2, a3, b0, b1);
                mma16816(acc[2 * j + 1], a0, a1, a2, a3, b2, b3);
            }
        }
        int cn = c + STAGES - 1;
        if (cn < NCHUNK) {
            int sn = cn & (STAGES - 1);
            if (tid < 160)
                cp_async16(a_dst0 + sn * ASTG, A + (size_t)a_gr * K + cn * 16 + a_h8);
            if (tid < 256) {
#pragma unroll
                for (int l = 0; l < 2; l++)
                    cp_async16(b_dst0[l] + sn * BSTG, W + (size_t)(cn * 16 + b_kr[l]) * Nn + b_c8[l]);
            }
        }
        cp_commit();
    }

    int tr = lane >> 2, tc = (lane & 3) << 1;
    int row0 = m0 + mt * 16 + tr;
    int row1 = row0 + 8;
#pragma unroll
    for (int j = 0; j < 16; j++) {
        int n0 = nh * 128 + j * 8 + tc;
        if (row0 < NN) {
            __half2 h = __floats2half2_rn(acc[j][0], acc[j][1]);
            *(__half2*)(C + (size_t)row0 * Nn + n0) = h;
        }
        if (row1 < NN) {
            __half2 h = __floats2half2_rn(acc[j][2], acc[j][3]);
            *(__half2*)(C + (size_t)row1 * Nn + n0) = h;
        }
    }
}

// ---------------- small GEMM for layer 5 (Nn=40): g_hwh[M,40] = A16 @ W5 ----------------
#define BM 80
#define BK 16
__global__ __launch_bounds__(320) void gemm40_kernel(int a_id, const float* __restrict__ W)
{
    const int K = FDIM, Nn = CDIM;
    const __half* A = hbuf(a_id);
    __half* C = g_hwh;

    __shared__ float As[BK][BM + 4];
    __shared__ float Bsm[BK][CDIM + 2];

    int tid = threadIdx.x;
    int tx = tid & 7;
    int ty = tid >> 3;
    int m0 = blockIdx.x * BM;

    float acc[2][5];
#pragma unroll
    for (int i = 0; i < 2; i++)
#pragma unroll
        for (int j = 0; j < 5; j++) acc[i][j] = 0.f;

    for (int k0 = 0; k0 < K; k0 += BK) {
        {
            int row = tid >> 2, kc = (tid & 3) << 2;
            uint2 u = *(const uint2*)(A + (size_t)(m0 + row) * K + k0 + kc);
            const __half2* hh = (const __half2*)&u;
            float2 f0 = __half22float2(hh[0]);
            float2 f1 = __half22float2(hh[1]);
            As[kc + 0][row] = f0.x;
            As[kc + 1][row] = f0.y;
            As[kc + 2][row] = f1.x;
            As[kc + 3][row] = f1.y;
        }
#pragma unroll
        for (int l = 0; l < 2; l++) {
            int idx = tid + l * 320;
            int kr = idx / CDIM, cc = idx - kr * CDIM;
            Bsm[kr][cc] = W[(size_t)(k0 + kr) * Nn + cc];
        }
        __syncthreads();
#pragma unroll
        for (int kk = 0; kk < BK; kk++) {
            float br[5];
#pragma unroll
            for (int j = 0; j < 5; j++) br[j] = Bsm[kk][tx * 5 + j];
            float a0 = As[kk][ty * 2 + 0];
            float a1 = As[kk][ty * 2 + 1];
#pragma unroll
            for (int j = 0; j < 5; j++) {
                acc[0][j] = fmaf(a0, br[j], acc[0][j]);
                acc[1][j] = fmaf(a1, br[j], acc[1][j]);
            }
        }
        __syncthreads();
    }
#pragma unroll
    for (int i = 0; i < 2; i++) {
        int row = m0 + ty * 2 + i;
        __half* cp = C + (size_t)row * Nn + tx * 5;
#pragma unroll
        for (int j = 0; j < 5; j++) cp[j] = __float2half_rn(acc[i][j]);
    }
}

// ---------------- aggregation (256 feats): warp per node, fp16 gather + fp16 out ----------------
__global__ void agg256_kernel(const float* __restrict__ bias, int out_id, int relu)
{
    int node = (blockIdx.x * blockDim.x + threadIdx.x) >> 5;
    if (node >= NN) return;
    __half* out = hbuf(out_id);
    int lane = threadIdx.x & 31;
    int beg = g_rowptr[node], end = g_rowptr[node + 1];

    float dv = g_dinv[node];
    float wself = dv * dv;

    float acc[8];
    {
        uint4 v = ((const uint4*)(g_hwh + (size_t)node * FDIM))[lane];
        const __half2* h = (const __half2*)&v;
#pragma unroll
        for (int q = 0; q < 4; q++) {
            float2 f = __half22float2(h[q]);
            acc[2 * q + 0] = wself * f.x;
            acc[2 * q + 1] = wself * f.y;
        }
    }

#pragma unroll 4
    for (int e = beg; e < end; e++) {
        int s = g_col[e];
        float w = g_wn[e];
        uint4 v = ((const uint4*)(g_hwh + (size_t)s * FDIM))[lane];
        const __half2* h = (const __half2*)&v;
#pragma unroll
        for (int q = 0; q < 4; q++) {
            float2 f = __half22float2(h[q]);
            acc[2 * q + 0] = fmaf(w, f.x, acc[2 * q + 0]);
            acc[2 * q + 1] = fmaf(w, f.y, acc[2 * q + 1]);
        }
    }
    float4 b0 = ((const float4*)bias)[lane * 2];
    float4 b1 = ((const float4*)bias)[lane * 2 + 1];
    float o[8] = {acc[0] + b0.x, acc[1] + b0.y, acc[2] + b0.z, acc[3] + b0.w,
                  acc[4] + b1.x, acc[5] + b1.y, acc[6] + b1.z, acc[7] + b1.w};
    if (relu) {
#pragma unroll
        for (int q = 0; q < 8; q++) o[q] = fmaxf(o[q], 0.f);
    }
    __half2 h2[4];
#pragma unroll
    for (int q = 0; q < 4; q++) h2[q] = __floats2half2_rn(o[2 * q], o[2 * q + 1]);
    *(uint4*)(out + (size_t)node * FDIM + lane * 8) = *(uint4*)h2;
}

// ---------------- layer5: aggregation (40 feats) + log_softmax fused ----------------
__global__ void agg40_lsm_kernel(const float* __restrict__ bias,
                                 float* __restrict__ out, int write_logits)
{
    int node = (blockIdx.x * blockDim.x + threadIdx.x) >> 5;
    if (node >= NN) return;
    int lane = threadIdx.x & 31;
    int beg = g_rowptr[node], end = g_rowptr[node + 1];

    float dv = g_dinv[node];
    float wself = dv * dv;
    const __half* hw = g_hwh;

    const __half* hp = hw + (size_t)node * CDIM;
    float a0 = wself * __half2float(hp[lane]);
    float a1 = (lane < CDIM - 32) ? wself * __half2float(hp[lane + 32]) : 0.f;

    for (int e = beg; e < end; e++) {
        int s = g_col[e];
        float w = g_wn[e];
        const __half* p = hw + (size_t)s * CDIM;
        a0 = fmaf(w, __half2float(p[lane]), a0);
        if (lane < CDIM - 32) a1 = fmaf(w, __half2float(p[lane + 32]), a1);
    }
    float v0 = a0 + bias[lane];
    float v1 = (lane < CDIM - 32) ? a1 + bias[lane + 32] : -1e30f;

    float m = fmaxf(v0, v1);
#pragma unroll
    for (int off = 16; off > 0; off >>= 1)
        m = fmaxf(m, __shfl_xor_sync(0xffffffffu, m, off));
    float s = __expf(v0 - m) + ((lane < CDIM - 32) ? __expf(v1 - m) : 0.f);
#pragma unroll
    for (int off = 16; off > 0; off >>= 1)
        s += __shfl_xor_sync(0xffffffffu, s, off);
    float lse = m + __logf(s);

    float* op = out + (size_t)node * CDIM;
    op[lane] = v0 - lse;
    if (lane < CDIM - 32) op[lane + 32] = v1 - lse;
    if (write_logits) {
        float* lo = out + (size_t)NN * CDIM + (size_t)node * CDIM;
        lo[lane] = v0;
        if (lane < CDIM - 32) lo[lane + 32] = v1;
    }
}

// ---------------- host ----------------
extern "C" void kernel_launch(void* const* d_in, const int* in_sizes, int n_in,
                              void* d_out, int out_size)
{
    const float* x  = (const float*)d_in[0];
    const void*  ei = d_in[1];
    const float* W1 = (const float*)d_in[2];  const float* b1 = (const float*)d_in[3];
    const float* W2 = (const float*)d_in[4];  const float* b2 = (const float*)d_in[5];
    const float* W3 = (const float*)d_in[6];  const float* b3 = (const float*)d_in[7];
    const float* W4 = (const float*)d_in[8];  const float* b4 = (const float*)d_in[9];
    const float* W5 = (const float*)d_in[10]; const float* b5 = (const float*)d_in[11];
    float* out = (float*)d_out;

    const int EB = (EE + 255) / 256;
    const int AGGB = (NN * 32 + 255) / 256;    // warp per node
    const int GB = (NN + GBM - 1) / GBM;       // 125 CTAs, single wave
    const int GB40 = NN / BM;                  // 125 CTAs

    // hbuf ids: 0=g_hAh, 1=g_hBh, 2=g_xh
    init_kernel<<<(NN + 255) / 256, 256>>>();                 // 1
    detect_kernel<<<64, 256>>>((const unsigned*)ei);          // 2 (16384 samples)
    conv_kernel<<<592, 256>>>(x, W1, W2, W3, W4);             // 3
    gemm_kernel<<<GB, 320>>>(2, 0);                           // 4  <- profiled
    count_deg_kernel<<<EB, 256>>>(ei);                        // 5
    scan1_kernel<<<40, 256>>>();                              // 6
    scan2_kernel<<<1, 32>>>();                                // 7
    scan3_kernel<<<40, 256>>>();                              // 8
    fill_kernel<<<EB, 256>>>(ei);                             // 9
    agg256_kernel<<<AGGB, 256>>>(b1, 0, 1);                   // 10

    gemm_kernel<<<GB, 320>>>(0, 1);
    agg256_kernel<<<AGGB, 256>>>(b2, 1, 1);
    gemm_kernel<<<GB, 320>>>(1, 2);
    agg256_kernel<<<AGGB, 256>>>(b3, 0, 1);
    gemm_kernel<<<GB, 320>>>(0, 3);
    agg256_kernel<<<AGGB, 256>>>(b4, 1, 1);
    gemm40_kernel<<<GB40, 320>>>(1, W5);
    int write_logits = (out_size >= 2 * NN * CDIM) ? 1 : 0;
    agg40_lsm_kernel<<<AGGB, 256>>>(b5, out, write_logits);

    (void)in_sizes; (void)n_in;
}